// round 3
// baseline (speedup 1.0000x reference)
#include <cuda_runtime.h>

#define B_   16
#define C_   64
#define H_   128
#define W_   128
#define E_   8
#define OC_  64
#define NP   16            // patches per spatial dim (128/8)
#define GFEAT 6144         // gate input dim = (64 + 32) * 64

// per-patch gate probabilities [B][ph][pw][E]
__device__ float g_gates[B_ * NP * NP * E_];

// ---------------- packed f32x2 helpers (sm_103a FFMA2 path) ----------------
__device__ __forceinline__ unsigned long long pack2(float lo, float hi) {
    unsigned long long r;
    asm("mov.b64 %0, {%1, %2};" : "=l"(r) : "f"(lo), "f"(hi));
    return r;
}
__device__ __forceinline__ unsigned long long fma2(unsigned long long a,
                                                   unsigned long long b,
                                                   unsigned long long c) {
    unsigned long long d;
    asm("fma.rn.f32x2 %0, %1, %2, %3;" : "=l"(d) : "l"(a), "l"(b), "l"(c));
    return d;
}

// ---------------- gating kernel ----------------
// One block per (patch, batch). 8 warps = 8 experts; warp-reduced dot product
// over the 6144-dim gate input (4096 pixel features + 2048 Fourier features).
__global__ void gate_kernel(const float* __restrict__ x,
                            const float* __restrict__ gw,
                            const float* __restrict__ gb) {
    int b  = blockIdx.y;
    int ph = blockIdx.x >> 4;
    int pw = blockIdx.x & 15;
    int tid  = threadIdx.x;
    int e    = tid >> 5;
    int lane = tid & 31;

    const float PI = 3.14159265358979323846f;
    const float* gwe = gw + e * GFEAT;
    const float* xb  = x + (size_t)b * C_ * H_ * W_;
    float cy = (ph + 0.5f) * (1.0f / 16.0f);
    float cx = (pw + 0.5f) * (1.0f / 16.0f);

    float acc = 0.f;
    for (int i = lane; i < GFEAT; i += 32) {
        int ch = i >> 6;
        int r  = i & 63;
        float v;
        if (ch < C_) {
            int py = r >> 3, px = r & 7;
            v = xb[ch * (H_ * W_) + (ph * 8 + py) * W_ + (pw * 8 + px)];
        } else {
            int pc  = ch - C_;        // 0..31
            int grp = pc >> 3;        // 0: sin(fy) 1: cos(fy) 2: sin(fx) 3: cos(fx)
            int j   = pc & 7;
            float f = exp2f((float)j) * PI;
            float a = (grp < 2 ? cy : cx) * f;
            v = (grp & 1) ? cosf(a) : sinf(a);
        }
        acc += v * gwe[i];
    }
    #pragma unroll
    for (int o = 16; o > 0; o >>= 1)
        acc += __shfl_xor_sync(0xffffffffu, acc, o);

    __shared__ float logit[E_];
    if (lane == 0) logit[e] = acc + gb[e];
    __syncthreads();

    if (tid == 0) {
        float m = logit[0];
        #pragma unroll
        for (int i = 1; i < E_; i++) m = fmaxf(m, logit[i]);
        float ex[E_];
        float s = 0.f;
        #pragma unroll
        for (int i = 0; i < E_; i++) { ex[i] = expf(logit[i] - m); s += ex[i]; }
        float inv = 1.f / s;
        int base = ((b * NP + ph) * NP + pw) * E_;
        #pragma unroll
        for (int i = 0; i < E_; i++) g_gates[base + i] = ex[i] * inv;
    }
}

// ---------------- fused conv + gated combine ----------------
// Block = one (batch, 16x16 pixel tile). x tile (+1 halo) staged in SMEM;
// weights streamed per (expert, 32-oc chunk) into SMEM laid out so a single
// broadcast LDS.128 yields 2 packed f32x2 weight pairs. Each thread owns one
// pixel and 32 packed output-channel accumulators; the per-expert relu+gate
// combine happens in registers (intermediate y never touches HBM).
#define XS_ST     18                    // x tile row stride (floats)
#define XS_CH     (18 * 18)             // 324 floats per channel
#define XS_FLOATS (C_ * XS_CH)          // 20736
#define WS_ST     40                    // weight row stride (floats), 160B -> 16B aligned
#define WS_FLOATS (576 * WS_ST)         // 23040
#define SB_FLOATS (E_ * OC_)            // 512 biases
#define SMEM_FLOATS (XS_FLOATS + WS_FLOATS + SB_FLOATS)
#define SMEM_BYTES  (SMEM_FLOATS * 4)   // 177152 B

__global__ __launch_bounds__(256, 1)
void moe_conv_kernel(const float* __restrict__ x,
                     const float* __restrict__ ew,
                     const float* __restrict__ eb,
                     float* __restrict__ out) {
    extern __shared__ float smem[];
    float* xs    = smem;
    float* ws    = smem + XS_FLOATS;
    float* sbias = ws + WS_FLOATS;

    int tid = threadIdx.x;
    int tx = tid & 15, ty = tid >> 4;
    int bx = blockIdx.x, by = blockIdx.y, b = blockIdx.z;
    int gx = bx * 16 + tx;
    int gy = by * 16 + ty;

    // --- load x tile with halo (zero-padded 'SAME' boundary) ---
    const float* xb = x + (size_t)b * C_ * H_ * W_;
    for (int idx = tid; idx < XS_FLOATS; idx += 256) {
        int c  = idx / XS_CH;
        int r  = idx - c * XS_CH;
        int yy = r / XS_ST;
        int xx = r - yy * XS_ST;
        int sy = by * 16 - 1 + yy;
        int sx = bx * 16 - 1 + xx;
        float v = 0.f;
        if (sy >= 0 && sy < H_ && sx >= 0 && sx < W_)
            v = xb[c * (H_ * W_) + sy * W_ + sx];
        xs[idx] = v;
    }
    for (int i = tid; i < SB_FLOATS; i += 256) sbias[i] = eb[i];

    const int gbase = ((b * NP + (gy >> 3)) * NP + (gx >> 3)) * E_;
    const int xoff  = ty * XS_ST + tx;     // halo offset: conv tap (dy,dx) reads (ty+dy, tx+dx)

    for (int occ = 0; occ < 2; occ++) {
        const int oc0 = occ * 32;
        float outc[32];
        #pragma unroll
        for (int j = 0; j < 32; j++) outc[j] = 0.f;

        for (int e = 0; e < E_; e++) {
            __syncthreads();   // protect ws (and first time: xs/sbias) before refill
            // stage weights: global [e][oc][c][3][3] contiguous chunk -> ws[ck][ocl]
            const float* wsrc = ew + ((size_t)(e * OC_ + oc0)) * 576;
            for (int idx = tid; idx < 32 * 576; idx += 256) {
                int ocl = idx / 576;
                int ck  = idx - ocl * 576;
                ws[ck * WS_ST + ocl] = wsrc[idx];
            }
            __syncthreads();

            unsigned long long acc[16];
            #pragma unroll
            for (int p = 0; p < 16; p++) acc[p] = 0ull;

            const float* xc = xs + xoff;
            const ulonglong2* wrow = (const ulonglong2*)ws;  // 16B-aligned rows (WS_ST=40)

            #pragma unroll 1
            for (int c = 0; c < C_; c++) {
                #pragma unroll
                for (int k = 0; k < 9; k++) {
                    const int dy = k / 3, dx = k - (k / 3) * 3;
                    float xv = xc[c * XS_CH + dy * XS_ST + dx];
                    unsigned long long xx2 = pack2(xv, xv);
                    const ulonglong2* wp = wrow + (c * 9 + k) * (WS_ST / 4);
                    #pragma unroll
                    for (int m = 0; m < 8; m++) {
                        ulonglong2 wv = wp[m];            // broadcast LDS.128: 2 oc-pairs
                        acc[2 * m]     = fma2(xx2, wv.x, acc[2 * m]);
                        acc[2 * m + 1] = fma2(xx2, wv.y, acc[2 * m + 1]);
                    }
                }
            }

            const float g = g_gates[gbase + e];
            #pragma unroll
            for (int p = 0; p < 16; p++) {
                float lo = __uint_as_float((unsigned)(acc[p] & 0xffffffffu));
                float hi = __uint_as_float((unsigned)(acc[p] >> 32));
                lo = fmaxf(lo + sbias[e * OC_ + oc0 + 2 * p], 0.f);
                hi = fmaxf(hi + sbias[e * OC_ + oc0 + 2 * p + 1], 0.f);
                outc[2 * p]     = fmaf(g, lo, outc[2 * p]);
                outc[2 * p + 1] = fmaf(g, hi, outc[2 * p + 1]);
            }
        }

        #pragma unroll
        for (int j = 0; j < 32; j++) {
            out[(((size_t)b * OC_ + oc0 + j) * H_ + gy) * W_ + gx] = outc[j];
        }
    }
}

// ---------------- launch ----------------
extern "C" void kernel_launch(void* const* d_in, const int* in_sizes, int n_in,
                              void* d_out, int out_size) {
    const float* x  = (const float*)d_in[0];  // [16,64,128,128]
    const float* ew = (const float*)d_in[1];  // [8,64,64,3,3]
    const float* eb = (const float*)d_in[2];  // [8,64]
    const float* gw = (const float*)d_in[3];  // [8,6144]
    const float* gb = (const float*)d_in[4];  // [8]
    float* out = (float*)d_out;               // [16,64,128,128]

    gate_kernel<<<dim3(NP * NP, B_), 256>>>(x, gw, gb);

    cudaFuncSetAttribute(moe_conv_kernel,
                         cudaFuncAttributeMaxDynamicSharedMemorySize, SMEM_BYTES);
    moe_conv_kernel<<<dim3(W_ / 16, H_ / 16, B_), 256, SMEM_BYTES>>>(x, ew, eb, out);
}

// round 5
// speedup vs baseline: 1.3654x; 1.3654x over previous
#include <cuda_runtime.h>

#define B_   16
#define C_   64
#define H_   128
#define W_   128
#define E_   8
#define OC_  64
#define NP   16            // patches per spatial dim (128/8)
#define GFEAT 6144         // gate input dim = (64 + 32) * 64

// per-patch gate probabilities [B][ph][pw][E]
__device__ float g_gates[B_ * NP * NP * E_];

// ---------------- packed f32x2 helpers (sm_103a FFMA2 path) ----------------
__device__ __forceinline__ unsigned long long pack2(float lo, float hi) {
    unsigned long long r;
    asm("mov.b64 %0, {%1, %2};" : "=l"(r) : "f"(lo), "f"(hi));
    return r;
}
__device__ __forceinline__ unsigned long long fma2(unsigned long long a,
                                                   unsigned long long b,
                                                   unsigned long long c) {
    unsigned long long d;
    asm("fma.rn.f32x2 %0, %1, %2, %3;" : "=l"(d) : "l"(a), "l"(b), "l"(c));
    return d;
}

// ---------------- gating kernel ----------------
__global__ void gate_kernel(const float* __restrict__ x,
                            const float* __restrict__ gw,
                            const float* __restrict__ gb) {
    int b  = blockIdx.y;
    int ph = blockIdx.x >> 4;
    int pw = blockIdx.x & 15;
    int tid  = threadIdx.x;
    int e    = tid >> 5;
    int lane = tid & 31;

    const float PI = 3.14159265358979323846f;
    const float* gwe = gw + e * GFEAT;
    const float* xb  = x + (size_t)b * C_ * H_ * W_;
    float cy = (ph + 0.5f) * (1.0f / 16.0f);
    float cx = (pw + 0.5f) * (1.0f / 16.0f);

    float acc = 0.f;
    for (int i = lane; i < GFEAT; i += 32) {
        int ch = i >> 6;
        int r  = i & 63;
        float v;
        if (ch < C_) {
            int py = r >> 3, px = r & 7;
            v = xb[ch * (H_ * W_) + (ph * 8 + py) * W_ + (pw * 8 + px)];
        } else {
            int pc  = ch - C_;        // 0..31
            int grp = pc >> 3;        // 0: sin(fy) 1: cos(fy) 2: sin(fx) 3: cos(fx)
            int j   = pc & 7;
            float f = exp2f((float)j) * PI;
            float a = (grp < 2 ? cy : cx) * f;
            v = (grp & 1) ? cosf(a) : sinf(a);
        }
        acc += v * gwe[i];
    }
    #pragma unroll
    for (int o = 16; o > 0; o >>= 1)
        acc += __shfl_xor_sync(0xffffffffu, acc, o);

    __shared__ float logit[E_];
    if (lane == 0) logit[e] = acc + gb[e];
    __syncthreads();

    if (tid == 0) {
        float m = logit[0];
        #pragma unroll
        for (int i = 1; i < E_; i++) m = fmaxf(m, logit[i]);
        float ex[E_];
        float s = 0.f;
        #pragma unroll
        for (int i = 0; i < E_; i++) { ex[i] = expf(logit[i] - m); s += ex[i]; }
        float inv = 1.f / s;
        int base = ((b * NP + ph) * NP + pw) * E_;
        #pragma unroll
        for (int i = 0; i < E_; i++) g_gates[base + i] = ex[i] * inv;
    }
}

// ---------------- fused conv + gated combine (register-blocked) ----------------
// Block = (batch, 16-wide x 32-tall pixel tile), 256 threads. Each thread owns
// TWO vertically adjacent pixels and a 16-oc chunk: weight LDS amortized over
// 2 pixels, and the 2 pixels' 9-tap stencils share 12 distinct x values per
// channel (4 rows x 3 cols). Inner loop: ~5.3 LDS per 16 FMA2 -> FMA2-bound.
#define TW_  16
#define TH_  32
#define XS_ST     18                     // x tile col stride
#define XS_CH     (34 * 18)              // 612 floats per channel (34 rows halo)
#define XS_FLOATS (C_ * XS_CH)           // 39168
#define WS_FLOATS (576 * 16)             // 9216: [k=576][ocl=16]
#define SB_FLOATS (E_ * OC_)             // 512
#define SMEM_FLOATS (XS_FLOATS + WS_FLOATS + SB_FLOATS)
#define SMEM_BYTES  (SMEM_FLOATS * 4)    // 195,584 B

__global__ __launch_bounds__(256, 1)
void moe_conv_kernel(const float* __restrict__ x,
                     const float* __restrict__ ew,
                     const float* __restrict__ eb,
                     float* __restrict__ out) {
    extern __shared__ float smem[];
    float* xs    = smem;
    float* ws    = smem + XS_FLOATS;      // 16B-aligned (39168*4 % 16 == 0)
    float* sbias = ws + WS_FLOATS;

    int tid = threadIdx.x;
    int tx = tid & 15, ty = tid >> 4;     // ty in 0..15, covers rows 2ty, 2ty+1
    int bx = blockIdx.x, by = blockIdx.y, b = blockIdx.z;

    // --- stage x tile with halo (zero-padded SAME boundary) ---
    const float* xb = x + (size_t)b * C_ * H_ * W_;
    for (int idx = tid; idx < XS_FLOATS; idx += 256) {
        int c  = idx / XS_CH;
        int r  = idx - c * XS_CH;
        int yy = r / XS_ST;
        int xx = r - yy * XS_ST;
        int sy = by * TH_ - 1 + yy;
        int sx = bx * TW_ - 1 + xx;
        float v = 0.f;
        if (sy >= 0 && sy < H_ && sx >= 0 && sx < W_)
            v = xb[c * (H_ * W_) + sy * W_ + sx];
        xs[idx] = v;
    }
    for (int i = tid; i < SB_FLOATS; i += 256) sbias[i] = eb[i];

    const int gx  = bx * TW_ + tx;
    const int gy0 = by * TH_ + 2 * ty;    // even -> both pixels in same 8x8 patch
    const int gbase = ((b * NP + (gy0 >> 3)) * NP + (gx >> 3)) * E_;
    const float* xbase = xs + (2 * ty) * XS_ST + tx;

    for (int occ = 0; occ < 4; occ++) {           // 16-oc chunks
        float outc[2][16];
        #pragma unroll
        for (int p = 0; p < 2; p++)
            #pragma unroll
            for (int j = 0; j < 16; j++) outc[p][j] = 0.f;

        for (int e = 0; e < E_; e++) {
            __syncthreads();   // protect ws readers (and first pass: xs/sbias)
            // stage weights: global [e][oc][c][3][3] -> ws[k][ocl]
            const float* wsrc = ew + ((size_t)(e * OC_ + occ * 16)) * 576;
            for (int idx = tid; idx < WS_FLOATS; idx += 256) {
                int ocl = idx / 576;
                int ck  = idx - ocl * 576;
                ws[ck * 16 + ocl] = wsrc[idx];
            }
            __syncthreads();

            unsigned long long acc[2][8];
            #pragma unroll
            for (int p = 0; p < 2; p++)
                #pragma unroll
                for (int m = 0; m < 8; m++) acc[p][m] = 0ull;

            #pragma unroll 1
            for (int c = 0; c < C_; c++) {
                const float* xc = xbase + c * XS_CH;
                float xv[4][3];                    // 12 shared taps for 2 pixels
                #pragma unroll
                for (int r = 0; r < 4; r++)
                    #pragma unroll
                    for (int j = 0; j < 3; j++)
                        xv[r][j] = xc[r * XS_ST + j];

                #pragma unroll
                for (int k = 0; k < 9; k++) {
                    const int dy = k / 3, dx = k - (k / 3) * 3;
                    const ulonglong2* wp =
                        (const ulonglong2*)(ws + (c * 9 + k) * 16);
                    ulonglong2 wa = wp[0];         // 4x broadcast LDS.128 = 16 ocs
                    ulonglong2 wb = wp[1];
                    ulonglong2 wc2 = wp[2];
                    ulonglong2 wd = wp[3];
                    #pragma unroll
                    for (int p = 0; p < 2; p++) {
                        float xvv = xv[dy + p][dx];
                        unsigned long long xx2 = pack2(xvv, xvv);
                        acc[p][0] = fma2(xx2, wa.x,  acc[p][0]);
                        acc[p][1] = fma2(xx2, wa.y,  acc[p][1]);
                        acc[p][2] = fma2(xx2, wb.x,  acc[p][2]);
                        acc[p][3] = fma2(xx2, wb.y,  acc[p][3]);
                        acc[p][4] = fma2(xx2, wc2.x, acc[p][4]);
                        acc[p][5] = fma2(xx2, wc2.y, acc[p][5]);
                        acc[p][6] = fma2(xx2, wd.x,  acc[p][6]);
                        acc[p][7] = fma2(xx2, wd.y,  acc[p][7]);
                    }
                }
            }

            const float g = g_gates[gbase + e];
            #pragma unroll
            for (int p = 0; p < 2; p++)
                #pragma unroll
                for (int m = 0; m < 8; m++) {
                    float lo = __uint_as_float((unsigned)(acc[p][m] & 0xffffffffu));
                    float hi = __uint_as_float((unsigned)(acc[p][m] >> 32));
                    lo = fmaxf(lo + sbias[e * OC_ + occ * 16 + 2 * m], 0.f);
                    hi = fmaxf(hi + sbias[e * OC_ + occ * 16 + 2 * m + 1], 0.f);
                    outc[p][2 * m]     = fmaf(g, lo, outc[p][2 * m]);
                    outc[p][2 * m + 1] = fmaf(g, hi, outc[p][2 * m + 1]);
                }
        }

        #pragma unroll
        for (int p = 0; p < 2; p++)
            #pragma unroll
            for (int j = 0; j < 16; j++)
                out[(((size_t)b * OC_ + occ * 16 + j) * H_ + gy0 + p) * W_ + gx] =
                    outc[p][j];
    }
}

// ---------------- launch ----------------
extern "C" void kernel_launch(void* const* d_in, const int* in_sizes, int n_in,
                              void* d_out, int out_size) {
    const float* x  = (const float*)d_in[0];  // [16,64,128,128]
    const float* ew = (const float*)d_in[1];  // [8,64,64,3,3]
    const float* eb = (const float*)d_in[2];  // [8,64]
    const float* gw = (const float*)d_in[3];  // [8,6144]
    const float* gb = (const float*)d_in[4];  // [8]
    float* out = (float*)d_out;               // [16,64,128,128]

    gate_kernel<<<dim3(NP * NP, B_), 256>>>(x, gw, gb);

    cudaFuncSetAttribute(moe_conv_kernel,
                         cudaFuncAttributeMaxDynamicSharedMemorySize, SMEM_BYTES);
    moe_conv_kernel<<<dim3(W_ / TW_, H_ / TH_, B_), 256, SMEM_BYTES>>>(x, ew, eb, out);
}

// round 11
// speedup vs baseline: 3.4653x; 2.5379x over previous
#include <cuda_runtime.h>
#include <cuda_bf16.h>
#include <cstdint>

#define B_   16
#define C_   64
#define H_   128
#define W_   128
#define E_   8
#define OC_  64
#define NTOT 512           // E*OC
#define NP   16
#define GFEAT 6144

// ---------------- device scratch (alloc-free rule: __device__ globals) ----
__device__ __nv_bfloat16 g_xh[(size_t)B_ * H_ * W_ * C_];   // NHWC hi
__device__ __nv_bfloat16 g_xl[(size_t)B_ * H_ * W_ * C_];   // NHWC lo
__device__ __nv_bfloat16 g_wh[9 * NTOT * C_];               // [tap][n][c] hi
__device__ __nv_bfloat16 g_wl[9 * NTOT * C_];               // [tap][n][c] lo
__device__ float g_gates[B_ * NP * NP * E_];

// ---------------- helpers ----------------
__device__ __forceinline__ uint32_t smem_u32(const void* p) {
    uint32_t a;
    asm("{ .reg .u64 t; cvta.to.shared.u64 t, %1; cvt.u32.u64 %0, t; }"
        : "=r"(a) : "l"(p));
    return a;
}
__device__ __forceinline__ void ldsm4(uint32_t* r, uint32_t addr) {
    asm volatile("ldmatrix.sync.aligned.m8n8.x4.shared.b16 {%0,%1,%2,%3}, [%4];"
        : "=r"(r[0]), "=r"(r[1]), "=r"(r[2]), "=r"(r[3]) : "r"(addr));
}
__device__ __forceinline__ void mma16816(float* c, const uint32_t* a,
                                         const uint32_t* b) {
    asm volatile(
        "mma.sync.aligned.m16n8k16.row.col.f32.bf16.bf16.f32 "
        "{%0,%1,%2,%3}, {%4,%5,%6,%7}, {%8,%9}, {%0,%1,%2,%3};"
        : "+f"(c[0]), "+f"(c[1]), "+f"(c[2]), "+f"(c[3])
        : "r"(a[0]), "r"(a[1]), "r"(a[2]), "r"(a[3]), "r"(b[0]), "r"(b[1]));
}
#define SW(o) ((o) ^ (((o) >> 3) & 0x70))

// ---------------- smem layout (bytes) ----------------
#define SM_GATES 0                       // 128 floats
#define SM_BIAS  512                     // 512 floats
#define SM_A     4096                    // 2(hf) * 4 rows * 130 px * 128B = 133120
#define SM_B     (SM_A + 133120)         // 137216 (1024-aligned)
#define SMEM_TOTAL (SM_B + 8192)         // 145408

// ---------------- prep kernels ----------------
__global__ void prep_x(const float* __restrict__ x) {
    int y = blockIdx.x, b = blockIdx.y, tid = threadIdx.x;
    __shared__ float s[C_ * W_];
    for (int i = tid; i < C_ * W_; i += 256)
        s[i] = x[((size_t)(b * C_ + (i >> 7)) * H_ + y) * W_ + (i & 127)];
    __syncthreads();
    for (int i = tid; i < W_ * C_; i += 256) {
        int xx = i >> 6, c = i & 63;
        float f = s[c * W_ + xx];
        __nv_bfloat16 h = __float2bfloat16(f);
        __nv_bfloat16 l = __float2bfloat16(f - __bfloat162float(h));
        size_t o = ((size_t)(b * H_ + y) * W_ + xx) * C_ + c;
        g_xh[o] = h; g_xl[o] = l;
    }
}

__global__ void prep_w(const float* __restrict__ ew) {
    int idx = blockIdx.x * 256 + threadIdx.x;          // 9*512*64 = 294912
    if (idx >= 9 * NTOT * C_) return;
    int tap = idx / (NTOT * C_);
    int rem = idx - tap * (NTOT * C_);
    int n = rem >> 6, c = rem & 63;
    float f = ew[((size_t)n * C_ + c) * 9 + tap];
    __nv_bfloat16 h = __float2bfloat16(f);
    __nv_bfloat16 l = __float2bfloat16(f - __bfloat162float(h));
    g_wh[idx] = h; g_wl[idx] = l;                      // [tap][n][c]
}

// ---------------- gating kernel (unchanged, proven) ----------------
__global__ void gate_kernel(const float* __restrict__ x,
                            const float* __restrict__ gw,
                            const float* __restrict__ gb) {
    int b = blockIdx.y, ph = blockIdx.x >> 4, pw = blockIdx.x & 15;
    int tid = threadIdx.x, e = tid >> 5, lane = tid & 31;
    const float PI = 3.14159265358979323846f;
    const float* gwe = gw + e * GFEAT;
    const float* xb  = x + (size_t)b * C_ * H_ * W_;
    float cy = (ph + 0.5f) / 16.0f, cx = (pw + 0.5f) / 16.0f;
    float acc = 0.f;
    for (int i = lane; i < GFEAT; i += 32) {
        int ch = i >> 6, r = i & 63;
        float v;
        if (ch < C_) {
            v = xb[ch * (H_ * W_) + (ph * 8 + (r >> 3)) * W_ + (pw * 8 + (r & 7))];
        } else {
            int pc = ch - C_, grp = pc >> 3, j = pc & 7;
            float a = (grp < 2 ? cy : cx) * exp2f((float)j) * PI;
            v = (grp & 1) ? cosf(a) : sinf(a);
        }
        acc += v * gwe[i];
    }
    #pragma unroll
    for (int o = 16; o > 0; o >>= 1) acc += __shfl_xor_sync(0xffffffffu, acc, o);
    __shared__ float logit[E_];
    if (lane == 0) logit[e] = acc + gb[e];
    __syncthreads();
    if (tid == 0) {
        float m = logit[0];
        #pragma unroll
        for (int i = 1; i < E_; i++) m = fmaxf(m, logit[i]);
        float ex[E_], s = 0.f;
        #pragma unroll
        for (int i = 0; i < E_; i++) { ex[i] = expf(logit[i] - m); s += ex[i]; }
        float inv = 1.f / s;
        int base = ((b * NP + ph) * NP + pw) * E_;
        #pragma unroll
        for (int i = 0; i < E_; i++) g_gates[base + i] = ex[i] * inv;
    }
}

// ---------------- main HMMA kernel ----------------
// CTA = (batch, 2 image rows): M = 256 pixels. 16 warps: wm = wid>>1 (32-pixel
// strip; wm/4 selects image row), wn = wid&1 (32-oc half). Experts processed
// sequentially (N-chunk = 64 = one expert): per-chunk f32 accum in registers,
// relu+bias+gate combined into a persistent 32-float running accumulator.
// K = 9 taps x 64c x 3 split passes (Ah*Bh, Ah*Bl, Al*Bh).
__global__ void __launch_bounds__(512, 1)
moe_mma_kernel(const float* __restrict__ eb, float* __restrict__ out) {
    extern __shared__ char smem[];
    uint32_t sb = smem_u32(smem);
    float* gs = (float*)(smem + SM_GATES);
    float* bs = (float*)(smem + SM_BIAS);
    int tid = threadIdx.x, wid = tid >> 5, lane = tid & 31;
    int b = blockIdx.y, y0 = blockIdx.x * 2;
    int wm = wid >> 1, wn = wid & 1;
    int r  = wm >> 2;                  // image row within pair
    int x0 = (wm & 3) * 32;            // pixel strip start

    // gates for this patch row (y0 even -> y0,y0+1 share patch row)
    if (tid < 128)
        gs[tid] = g_gates[((b * NP + (y0 >> 3)) * NP + (tid >> 3)) * E_ + (tid & 7)];
    bs[tid] = eb[tid];

    // --- stage A: input rows y0-1..y0+2, 130 px, hi+lo, SW128, 128B/px ---
    for (int i = tid; i < 8320; i += 512) {     // 2 hf * 4 rows * 130 px * 8 chunks
        int hf = i / 4160, rem = i - hf * 4160;
        int sr = rem / 1040, rem2 = rem - sr * 1040;
        int px = rem2 >> 3, c16 = rem2 & 7;
        int yy = y0 - 1 + sr, xx = px - 1;
        uint4 v = make_uint4(0, 0, 0, 0);
        if (yy >= 0 && yy < H_ && xx >= 0 && xx < W_)
            v = *(const uint4*)((hf ? g_xl : g_xh)
                    + ((size_t)(b * H_ + yy) * W_ + xx) * C_ + c16 * 8);
        int loc = ((hf * 4 + sr) * 130 + px) * 128 + c16 * 16;
        *(uint4*)(smem + SM_A + SW(loc)) = v;
    }

    // per-lane ldmatrix address components
    int a_px = ((lane >> 3) & 1) * 8 + (lane & 7);   // A: m row select
    int a_ch = (lane >> 4) * 8;                      // A: k half
    int b_n  = ((lane >> 4) & 1) * 8 + (lane & 7);   // B: n row select
    int b_ch = ((lane >> 3) & 1) * 8;                // B: k half

    float run[2][4][4];
    #pragma unroll
    for (int im = 0; im < 2; im++)
        #pragma unroll
        for (int ng = 0; ng < 4; ng++)
            #pragma unroll
            for (int j = 0; j < 4; j++) run[im][ng][j] = 0.f;

    for (int e = 0; e < E_; e++) {
        float acc[2][4][4];
        #pragma unroll
        for (int im = 0; im < 2; im++)
            #pragma unroll
            for (int ng = 0; ng < 4; ng++)
                #pragma unroll
                for (int j = 0; j < 4; j++) acc[im][ng][j] = 0.f;

        for (int tap = 0; tap < 9; tap++) {
            int ky = tap / 3, kx = tap - ky * 3;
            for (int bh = 0; bh < 2; bh++) {         // 0: Bh (vs Ah,Al), 1: Bl (vs Ah)
                __syncthreads();                     // prior B consumers done
                {   // stage B tile: 64 oc rows x 64 c, 128B rows, SW128
                    const __nv_bfloat16* src =
                        (bh ? g_wl : g_wh) + ((size_t)tap * NTOT + e * 64) * C_;
                    int nl = tid >> 3, c16 = tid & 7;
                    uint4 v = *(const uint4*)(src + nl * C_ + c16 * 8);
                    *(uint4*)(smem + SM_B + SW(nl * 128 + c16 * 16)) = v;
                }
                __syncthreads();

                int nah = bh ? 1 : 2;
                #pragma unroll
                for (int kc = 0; kc < 4; kc++) {
                    uint32_t bf[2][4];
                    #pragma unroll
                    for (int ngq = 0; ngq < 2; ngq++) {
                        int boff = (wn * 32 + ngq * 16 + b_n) * 128
                                 + (kc * 16 + b_ch) * 2;
                        ldsm4(bf[ngq], sb + SM_B + SW(boff));
                    }
                    for (int ah = 0; ah < nah; ah++) {
                        #pragma unroll
                        for (int im = 0; im < 2; im++) {
                            int px = x0 + im * 16 + a_px + kx;   // stored idx = x+kx
                            int aoff = ((ah * 4 + r + ky) * 130 + px) * 128
                                     + (kc * 16 + a_ch) * 2;
                            uint32_t af[4];
                            ldsm4(af, sb + SM_A + SW(aoff));
                            #pragma unroll
                            for (int ng = 0; ng < 4; ng++)
                                mma16816(acc[im][ng], af, &bf[ng >> 1][(ng & 1) * 2]);
                        }
                    }
                }
            }
        }
        // ---- per-expert epilogue: relu + bias + gated accumulate ----
        #pragma unroll
        for (int im = 0; im < 2; im++) {
            int xa = x0 + im * 16 + (lane >> 2);
            float ga = gs[(xa >> 3) * 8 + e];
            float gb2 = gs[((xa + 8) >> 3) * 8 + e];
            #pragma unroll
            for (int ng = 0; ng < 4; ng++) {
                int oc0 = wn * 32 + ng * 8 + (lane & 3) * 2;
                float bb0 = bs[e * 64 + oc0], bb1 = bs[e * 64 + oc0 + 1];
                run[im][ng][0] += ga  * fmaxf(acc[im][ng][0] + bb0, 0.f);
                run[im][ng][1] += ga  * fmaxf(acc[im][ng][1] + bb1, 0.f);
                run[im][ng][2] += gb2 * fmaxf(acc[im][ng][2] + bb0, 0.f);
                run[im][ng][3] += gb2 * fmaxf(acc[im][ng][3] + bb1, 0.f);
            }
        }
    }

    // ---- final store ----
    int y = y0 + r;
    #pragma unroll
    for (int im = 0; im < 2; im++) {
        int xa = x0 + im * 16 + (lane >> 2);
        #pragma unroll
        for (int ng = 0; ng < 4; ng++) {
            int oc0 = wn * 32 + ng * 8 + (lane & 3) * 2;
            size_t o0 = (((size_t)b * OC_ + oc0) * H_ + y) * W_;
            out[o0 + xa]                       = run[im][ng][0];
            out[o0 + (size_t)H_ * W_ + xa]     = run[im][ng][1];
            out[o0 + xa + 8]                   = run[im][ng][2];
            out[o0 + (size_t)H_ * W_ + xa + 8] = run[im][ng][3];
        }
    }
}

// ---------------- launch ----------------
extern "C" void kernel_launch(void* const* d_in, const int* in_sizes, int n_in,
                              void* d_out, int out_size) {
    const float* x  = (const float*)d_in[0];  // [16,64,128,128]
    const float* ew = (const float*)d_in[1];  // [8,64,64,3,3]
    const float* eb = (const float*)d_in[2];  // [8,64]
    const float* gw = (const float*)d_in[3];  // [8,6144]
    const float* gb = (const float*)d_in[4];  // [8]
    float* out = (float*)d_out;               // [16,64,128,128]

    prep_x<<<dim3(H_, B_), 256>>>(x);
    prep_w<<<(9 * NTOT * C_ + 255) / 256, 256>>>(ew);
    gate_kernel<<<dim3(NP * NP, B_), 256>>>(x, gw, gb);

    cudaFuncSetAttribute(moe_mma_kernel,
                         cudaFuncAttributeMaxDynamicSharedMemorySize, SMEM_TOTAL);
    moe_mma_kernel<<<dim3(H_ / 2, B_), 512, SMEM_TOTAL>>>(eb, out);
}